// round 3
// baseline (speedup 1.0000x reference)
#include <cuda_runtime.h>
#include <math.h>

#define B   256
#define NF  10000
#define H   768
#define K   512
#define NT  10
#define TOK (B*K)

// ---------------- scratch (__device__ globals; no allocs allowed) ----------------
__device__ float g_vals[TOK];
__device__ int   g_fid[TOK];
__device__ int   g_empty[B];
__device__ float g_coef[NT*H];   // c_k[h]: Taylor coeffs of gelu(w1[h]*v + b1[h]) in v
__device__ float g_G[NT*H];      // G_k[d] = sum_h c_k[h]*w2[h,d] (+ b2[d] into k=0)

// ---------------- kernel 1a: per-h Taylor coefficients --------------------------
// gelu(z) = z*Phi(z).  gelu^{(k)}(beta) = phi(beta)*(-1)^k*(k*He_{k-2} - beta*He_{k-1}) for k>=2.
__global__ void coef_kernel(const float* __restrict__ w1, const float* __restrict__ b1) {
    int h = threadIdx.x;
    double a    = (double)w1[h];
    double beta = (double)b1[h];
    const double INV_SQRT2PI = 0.39894228040143267794;
    const double INV_SQRT2   = 0.70710678118654752440;
    double phi = INV_SQRT2PI * exp(-0.5 * beta * beta);
    double Phi = 0.5 * (1.0 + erf(beta * INV_SQRT2));
    double c[NT];
    c[0] = beta * Phi;                  // gelu(beta)
    c[1] = (Phi + beta * phi) * a;      // gelu'(beta) * a
    double He_km2 = 1.0;                // He_0
    double He_km1 = beta;               // He_1
    double fact = 1.0;
    double apow = a;
    for (int k = 2; k < NT; k++) {
        fact *= (double)k;
        apow *= a;
        double s  = (k & 1) ? -1.0 : 1.0;
        double gk = phi * s * ((double)k * He_km2 - beta * He_km1);
        c[k] = gk * apow / fact;
        double He_k = beta * He_km1 - (double)(k - 1) * He_km2;
        He_km2 = He_km1;
        He_km1 = He_k;
    }
    for (int k = 0; k < NT; k++) g_coef[k*H + h] = (float)c[k];
}

// ---------------- kernel 1b: G_k = w2^T c_k (+ b2 into k=0) ---------------------
__global__ void gvec_kernel(const float* __restrict__ w2, const float* __restrict__ b2) {
    int k = blockIdx.y;
    int d = blockIdx.x * blockDim.x + threadIdx.x;
    if (d >= H) return;
    const float* c = &g_coef[k*H];
    float acc = (k == 0) ? b2[d] : 0.0f;
#pragma unroll 8
    for (int h = 0; h < H; h++) acc = fmaf(c[h], w2[h*H + d], acc);
    g_G[k*H + d] = acc;
}

// ---------------- kernel 2: per-row top-512 (sorted, torch tie-break) -----------
// 64-bit key = (abs_bits << 32) | ~idx  -> strictly distinct, descending abs,
// ascending idx on abs ties (matches lax.top_k / torch.topk).
__global__ void __launch_bounds__(1024) topk_kernel(const float* __restrict__ x,
                                                    float* __restrict__ out,
                                                    int write_mask) {
    __shared__ float xrow[NF];
    __shared__ unsigned long long cand[K];
    __shared__ int wsum[32];
    __shared__ int stot;
    __shared__ int scnt;

    int b   = blockIdx.x;
    int tid = threadIdx.x;
    const float* xr = x + (size_t)b * NF;
    for (int i = tid; i < NF; i += 1024) xrow[i] = xr[i];
    if (tid == 0) scnt = 0;
    __syncthreads();

    unsigned long long keys[10];
#pragma unroll
    for (int r = 0; r < 10; r++) {
        int i = tid + r * 1024;
        unsigned long long kb = 0ull;
        if (i < NF) {
            unsigned int ab = __float_as_uint(fabsf(xrow[i]));
            kb = ((unsigned long long)ab << 32) | (unsigned int)(~i);
        }
        keys[r] = kb;
    }

    int lane = tid & 31, warp = tid >> 5;
    // bitwise binary search for the 512th-largest (distinct) key
    unsigned long long prefix = 0ull;
    for (int bit = 62; bit >= 0; bit--) {
        unsigned long long trial = prefix | (1ull << bit);
        int c = 0;
#pragma unroll
        for (int r = 0; r < 10; r++) c += (keys[r] >= trial) ? 1 : 0;
#pragma unroll
        for (int o = 16; o; o >>= 1) c += __shfl_down_sync(0xffffffffu, c, o);
        if (lane == 0) wsum[warp] = c;
        __syncthreads();
        if (tid == 0) {
            int t = 0;
#pragma unroll
            for (int w = 0; w < 32; w++) t += wsum[w];
            stot = t;
        }
        __syncthreads();
        if (stot >= K) prefix = trial;
    }

    // gather the exactly-512 keys >= pivot
#pragma unroll
    for (int r = 0; r < 10; r++) {
        if (keys[r] >= prefix) {
            int p = atomicAdd(&scnt, 1);
            cand[p] = keys[r];
        }
    }
    __syncthreads();

    // bitonic sort 512, descending
    for (int sz = 2; sz <= K; sz <<= 1) {
        for (int j = sz >> 1; j > 0; j >>= 1) {
            if (tid < K) {
                int ixj = tid ^ j;
                if (ixj > tid) {
                    unsigned long long av = cand[tid], bv = cand[ixj];
                    bool desc = ((tid & sz) == 0);
                    if (desc ? (av < bv) : (av > bv)) { cand[tid] = bv; cand[ixj] = av; }
                }
            }
            __syncthreads();
        }
    }

    int   active = 0;
    float val = 0.0f;
    int   fid = 0;
    if (tid < K) {
        unsigned long long key = cand[tid];
        unsigned int hi  = (unsigned int)(key >> 32);
        unsigned int idx = ~(unsigned int)key;
        active = (hi != 0u) ? 1 : 0;
        if (active) { val = xrow[idx]; fid = (int)idx + 1; }
    }
    int nact  = __syncthreads_count(active);
    int empty = (nact == 0) ? 1 : 0;
    if (tid < K) {
        g_vals[b*K + tid] = val;
        g_fid [b*K + tid] = fid;
        if (tid == 0) g_empty[b] = empty;
        if (write_mask) {
            float m = (float)active;
            if (tid == 0 && empty) m = 1.0f;
            out[(size_t)TOK * H + (size_t)b * K + tid] = m;
        }
    }
}

// ---------------- kernel 3: fused gather + poly value-proj + LayerNorm ----------
#define TPB_TOK 64
#define RPT     4
__global__ void __launch_bounds__(768, 2) fuse_kernel(const float* __restrict__ emb,
                                                      const float* __restrict__ lnw,
                                                      const float* __restrict__ lnb,
                                                      float* __restrict__ out) {
    __shared__ float red[2*RPT][25];
    __shared__ float fin[2*RPT];

    int d    = threadIdx.x;
    int base = blockIdx.x * TPB_TOK;
    float G[NT];
#pragma unroll
    for (int k = 0; k < NT; k++) G[k] = g_G[k*H + d];
    float lw = lnw[d], lb = lnb[d];
    int lane = d & 31, warp = d >> 5;

    for (int t0 = 0; t0 < TPB_TOK; t0 += RPT) {
        float h[RPT], s[2*RPT];
#pragma unroll
        for (int j = 0; j < RPT; j++) {
            int   tok = base + t0 + j;
            float v   = g_vals[tok];
            int   fid = g_fid[tok];
            float e   = __ldg(&emb[(size_t)fid * H + d]);
            float p   = G[NT-1];
#pragma unroll
            for (int k = NT - 2; k >= 0; k--) p = fmaf(p, v, G[k]);
            float hh = e + p;
            h[j]       = hh;
            s[j]       = hh;
            s[RPT + j] = hh * hh;
        }
#pragma unroll
        for (int o = 16; o; o >>= 1)
#pragma unroll
            for (int i = 0; i < 2*RPT; i++) s[i] += __shfl_down_sync(0xffffffffu, s[i], o);
        if (lane == 0)
#pragma unroll
            for (int i = 0; i < 2*RPT; i++) red[i][warp] = s[i];
        __syncthreads();
        if (d < 2*RPT) {
            float a = 0.0f;
#pragma unroll
            for (int w = 0; w < 24; w++) a += red[d][w];
            fin[d] = a;
        }
        __syncthreads();
#pragma unroll
        for (int j = 0; j < RPT; j++) {
            int   tok  = base + t0 + j;
            float mu   = fin[j] * (1.0f / H);
            float var  = fin[RPT + j] * (1.0f / H) - mu * mu;
            float rstd = rsqrtf(var + 1e-5f);
            float o    = (h[j] - mu) * rstd * lw + lb;
            if ((tok & (K - 1)) == 0) {
                if (g_empty[tok >> 9]) o = 0.0f;
            }
            out[(size_t)tok * H + d] = o;
        }
        __syncthreads();
    }
}

// ---------------- launch --------------------------------------------------------
extern "C" void kernel_launch(void* const* d_in, const int* in_sizes, int n_in,
                              void* d_out, int out_size) {
    const float* x   = (const float*)d_in[0];
    const float* emb = (const float*)d_in[1];
    const float* w1  = (const float*)d_in[2];
    const float* b1  = (const float*)d_in[3];
    const float* w2  = (const float*)d_in[4];
    const float* b2  = (const float*)d_in[5];
    const float* lnw = (const float*)d_in[6];
    const float* lnb = (const float*)d_in[7];
    float* out = (float*)d_out;

    int write_mask = (out_size >= TOK * H + TOK) ? 1 : 0;

    coef_kernel<<<1, H>>>(w1, b1);
    gvec_kernel<<<dim3((H + 127) / 128, NT), 128>>>(w2, b2);
    topk_kernel<<<B, 1024>>>(x, out, write_mask);
    fuse_kernel<<<TOK / TPB_TOK, 768>>>(emb, lnw, lnb, out);
}

// round 4
// speedup vs baseline: 2.7590x; 2.7590x over previous
#include <cuda_runtime.h>
#include <math.h>

#define B   256
#define NF  10000
#define H   768
#define K   512
#define NT  8
#define QN  (2*NT-1)
#define TOK (B*K)

// ---------------- scratch ----------------
__device__ float g_vals[TOK];
__device__ int   g_fid[TOK];
__device__ int   g_empty[B];
__device__ __align__(16) float g_coef[NT*H];
__device__ __align__(16) float g_G[NT*H];
__device__ float g_SG[NT];
__device__ float g_Q[QN];
__device__ float g_Se[NF+1];
__device__ float g_Se2[NF+1];
__device__ __align__(16) float g_D[(NF+1)*NT];
__device__ float4 g_tok[TOK];

// ---------------- kernel 1a: per-h Taylor coefficients + zero g_G ----------------
__global__ void coef_kernel(const float* __restrict__ w1, const float* __restrict__ b1) {
    int h = threadIdx.x;
#pragma unroll
    for (int k = 0; k < NT; k++) g_G[k*H + h] = 0.0f;   // zero for gvec atomics
    double a    = (double)w1[h];
    double beta = (double)b1[h];
    const double INV_SQRT2PI = 0.39894228040143267794;
    const double INV_SQRT2   = 0.70710678118654752440;
    double phi = INV_SQRT2PI * exp(-0.5 * beta * beta);
    double Phi = 0.5 * (1.0 + erf(beta * INV_SQRT2));
    double c[NT];
    c[0] = beta * Phi;
    c[1] = (Phi + beta * phi) * a;
    double He_km2 = 1.0, He_km1 = beta, fact = 1.0, apow = a;
    for (int k = 2; k < NT; k++) {
        fact *= (double)k;
        apow *= a;
        double s  = (k & 1) ? -1.0 : 1.0;
        double gk = phi * s * ((double)k * He_km2 - beta * He_km1);
        c[k] = gk * apow / fact;
        double He_k = beta * He_km1 - (double)(k - 1) * He_km2;
        He_km2 = He_km1; He_km1 = He_k;
    }
    for (int k = 0; k < NT; k++) g_coef[k*H + h] = (float)c[k];
}

// ---------------- kernel 1b: G_k = w2^T c_k (+ b2 into k=0), h-split + atomics ---
#define GV_HB 8
#define GV_HC (H / GV_HB)
__global__ void gvec_kernel(const float* __restrict__ w2, const float* __restrict__ b2) {
    __shared__ float sc[NT * GV_HC];
    int tid = threadIdx.x;                  // 128
    int d   = blockIdx.x * 128 + tid;
    int h0  = blockIdx.y * GV_HC;
    for (int i = tid; i < NT * GV_HC; i += 128) {
        int k = i / GV_HC, h = i % GV_HC;
        sc[i] = g_coef[k*H + h0 + h];
    }
    __syncthreads();
    float acc[NT];
#pragma unroll
    for (int k = 0; k < NT; k++) acc[k] = 0.0f;
#pragma unroll 4
    for (int h = 0; h < GV_HC; h++) {
        float w = w2[(size_t)(h0 + h) * H + d];
#pragma unroll
        for (int k = 0; k < NT; k++) acc[k] = fmaf(sc[k*GV_HC + h], w, acc[k]);
    }
    if (blockIdx.y == 0) acc[0] += b2[d];
#pragma unroll
    for (int k = 0; k < NT; k++) atomicAdd(&g_G[k*H + d], acc[k]);
}

// ---------------- kernel 1c: SG_k and Q_m (1 block, 768 threads) -----------------
__global__ void poly_stats_kernel() {
    __shared__ float s[NT + NT*(NT+1)/2];
    int d = threadIdx.x;
    int lane = d & 31;
    if (d < NT + NT*(NT+1)/2) s[d] = 0.0f;
    __syncthreads();
    float g[NT];
#pragma unroll
    for (int k = 0; k < NT; k++) g[k] = g_G[k*H + d];

#define BRED(slot, expr) { float _v = (expr); \
    _v += __shfl_down_sync(0xffffffffu, _v, 16); \
    _v += __shfl_down_sync(0xffffffffu, _v, 8);  \
    _v += __shfl_down_sync(0xffffffffu, _v, 4);  \
    _v += __shfl_down_sync(0xffffffffu, _v, 2);  \
    _v += __shfl_down_sync(0xffffffffu, _v, 1);  \
    if (lane == 0) atomicAdd(&s[slot], _v); }

#pragma unroll
    for (int k = 0; k < NT; k++) BRED(k, g[k]);
    {
        int idx = NT;
#pragma unroll
        for (int k = 0; k < NT; k++)
#pragma unroll
            for (int l = k; l < NT; l++) { BRED(idx, g[k]*g[l]); idx++; }
    }
    __syncthreads();
    if (d == 0) {
        for (int k = 0; k < NT; k++) g_SG[k] = s[k];
        float q[QN];
        for (int m = 0; m < QN; m++) q[m] = 0.0f;
        int idx = NT;
        for (int k = 0; k < NT; k++)
            for (int l = k; l < NT; l++) {
                q[k+l] += (k == l ? 1.0f : 2.0f) * s[idx];
                idx++;
            }
        for (int m = 0; m < QN; m++) g_Q[m] = q[m];
    }
}

// ---------------- kernel 1d: per-emb-row Se, Se2, D_k ----------------------------
__global__ void __launch_bounds__(192) emb_stats_kernel(const float* __restrict__ emb) {
    int dg = threadIdx.x;                   // dim group, 4 dims
    int lane = dg & 31, warp = dg >> 5;     // 6 warps
    float4 G[NT];
#pragma unroll
    for (int k = 0; k < NT; k++) G[k] = ((const float4*)g_G)[k*192 + dg];
    __shared__ float red[NT+2][7];
    const float4* emb4 = (const float4*)emb;

    for (int r = blockIdx.x; r <= NF; r += gridDim.x) {
        float4 e = emb4[(size_t)r * 192 + dg];
        float vals[NT+2];
        vals[0] = e.x + e.y + e.z + e.w;
        vals[1] = e.x*e.x + e.y*e.y + e.z*e.z + e.w*e.w;
#pragma unroll
        for (int k = 0; k < NT; k++)
            vals[2+k] = e.x*G[k].x + e.y*G[k].y + e.z*G[k].z + e.w*G[k].w;
#pragma unroll
        for (int i = 0; i < NT+2; i++) {
            float v = vals[i];
            v += __shfl_down_sync(0xffffffffu, v, 16);
            v += __shfl_down_sync(0xffffffffu, v, 8);
            v += __shfl_down_sync(0xffffffffu, v, 4);
            v += __shfl_down_sync(0xffffffffu, v, 2);
            v += __shfl_down_sync(0xffffffffu, v, 1);
            if (lane == 0) red[i][warp] = v;
        }
        __syncthreads();
        if (dg < NT+2) {
            float a = red[dg][0] + red[dg][1] + red[dg][2]
                    + red[dg][3] + red[dg][4] + red[dg][5];
            if (dg == 0)      g_Se[r]  = a;
            else if (dg == 1) g_Se2[r] = a;
            else              g_D[r*NT + (dg-2)] = a;
        }
        __syncthreads();
    }
}

// ---------------- kernel 2: per-row top-512 (sorted, torch tie-break) -----------
__global__ void __launch_bounds__(1024) topk_kernel(const float* __restrict__ x,
                                                    float* __restrict__ out,
                                                    int write_mask) {
    __shared__ float xrow[NF];
    __shared__ unsigned long long cand[K];
    __shared__ int wsum[32];
    __shared__ int s_ge;
    __shared__ int scnt;

    int b   = blockIdx.x;
    int tid = threadIdx.x;
    const float* xr = x + (size_t)b * NF;
    for (int i = tid; i < NF; i += 1024) xrow[i] = xr[i];
    if (tid == 0) scnt = 0;
    __syncthreads();

    unsigned long long keys[10];
#pragma unroll
    for (int r = 0; r < 10; r++) {
        int i = tid + r * 1024;
        unsigned long long kb = 0ull;
        if (i < NF) {
            unsigned int ab = __float_as_uint(fabsf(xrow[i]));
            kb = ((unsigned long long)ab << 32) | (unsigned int)(~i);
        }
        keys[r] = kb;
    }

    int lane = tid & 31, warp = tid >> 5;
    unsigned long long prefix = 0ull;
    for (int bit = 62; bit >= 0; bit--) {
        unsigned long long trial = prefix | (1ull << bit);
        int c = 0;
#pragma unroll
        for (int r = 0; r < 10; r++) c += (keys[r] >= trial) ? 1 : 0;
#pragma unroll
        for (int o = 16; o; o >>= 1) c += __shfl_down_sync(0xffffffffu, c, o);
        if (lane == 0) wsum[warp] = c;
        __syncthreads();
        if (warp == 0) {
            int t = wsum[lane];
#pragma unroll
            for (int o = 16; o; o >>= 1) t += __shfl_down_sync(0xffffffffu, t, o);
            if (lane == 0) s_ge = t;
        }
        __syncthreads();
        if (s_ge >= K) prefix = trial;
    }

#pragma unroll
    for (int r = 0; r < 10; r++) {
        if (keys[r] >= prefix) {
            int p = atomicAdd(&scnt, 1);
            if (p < K) cand[p] = keys[r];
        }
    }
    __syncthreads();

    for (int sz = 2; sz <= K; sz <<= 1) {
        for (int j = sz >> 1; j > 0; j >>= 1) {
            if (tid < K) {
                int ixj = tid ^ j;
                if (ixj > tid) {
                    unsigned long long av = cand[tid], bv = cand[ixj];
                    bool desc = ((tid & sz) == 0);
                    if (desc ? (av < bv) : (av > bv)) { cand[tid] = bv; cand[ixj] = av; }
                }
            }
            __syncthreads();
        }
    }

    int   active = 0;
    float val = 0.0f;
    int   fid = 0;
    if (tid < K) {
        unsigned long long key = cand[tid];
        unsigned int hi  = (unsigned int)(key >> 32);
        unsigned int idx = ~(unsigned int)key;
        active = (hi != 0u) ? 1 : 0;
        if (active) { val = xrow[idx]; fid = (int)idx + 1; }
    }
    int nact  = __syncthreads_count(active);
    int empty = (nact == 0) ? 1 : 0;
    if (tid < K) {
        g_vals[b*K + tid] = val;
        g_fid [b*K + tid] = fid;
        if (tid == 0) g_empty[b] = empty;
        if (write_mask) {
            float m = (float)active;
            if (tid == 0 && empty) m = 1.0f;
            out[(size_t)TOK * H + (size_t)b * K + tid] = m;
        }
    }
}

// ---------------- kernel 3: closed-form per-token LN statistics ------------------
__global__ void token_stats_kernel() {
    int tok = blockIdx.x * 256 + threadIdx.x;
    float v   = g_vals[tok];
    int   fid = g_fid[tok];

    // sum(h) = Se + Horner(SG, v)
    float ps = g_SG[NT-1];
#pragma unroll
    for (int k = NT-2; k >= 0; k--) ps = fmaf(ps, v, g_SG[k]);
    float sumh = g_Se[fid] + ps;

    // sum(h^2) = Se2 + 2*Horner(D[fid], v) + Horner(Q, v)
    const float4* D4 = (const float4*)&g_D[fid * NT];
    float4 d0 = D4[0], d1 = D4[1];
    float D[NT] = {d0.x, d0.y, d0.z, d0.w, d1.x, d1.y, d1.z, d1.w};
    float pd = D[NT-1];
#pragma unroll
    for (int k = NT-2; k >= 0; k--) pd = fmaf(pd, v, D[k]);
    float pq = g_Q[QN-1];
#pragma unroll
    for (int m = QN-2; m >= 0; m--) pq = fmaf(pq, v, g_Q[m]);
    float sumh2 = g_Se2[fid] + 2.0f*pd + pq;

    float mu   = sumh * (1.0f / H);
    float var  = sumh2 * (1.0f / H) - mu * mu;
    float rstd = rsqrtf(var + 1e-5f);

    unsigned int enc = (unsigned int)fid;
    if ((tok & (K-1)) == 0 && g_empty[tok >> 9]) enc |= 0x80000000u;
    g_tok[tok] = make_float4(v, __uint_as_float(enc), mu, rstd);
}

// ---------------- kernel 4: fused gather + poly + LN (reduction-free, float4) ----
#define FU_TPB 64
__global__ void __launch_bounds__(192, 4) fuse_kernel(const float* __restrict__ emb,
                                                      const float* __restrict__ lnw,
                                                      const float* __restrict__ lnb,
                                                      float* __restrict__ out) {
    int dg = threadIdx.x;                   // 0..191 -> dims 4*dg..4*dg+3
    float4 G[NT];
#pragma unroll
    for (int k = 0; k < NT; k++) G[k] = ((const float4*)g_G)[k*192 + dg];
    float4 lw = ((const float4*)lnw)[dg];
    float4 lb = ((const float4*)lnb)[dg];
    const float4* emb4 = (const float4*)emb;
    float4* out4 = (float4*)out;

    int t0 = blockIdx.x * FU_TPB;
    for (int tt = t0; tt < t0 + FU_TPB; tt += 2) {
#pragma unroll
        for (int j = 0; j < 2; j++) {
            int tok = tt + j;
            float4 t = g_tok[tok];
            int enc = __float_as_int(t.y);
            float4 e = emb4[(size_t)(enc & 0x7fffffff) * 192 + dg];
            float v = t.x, mu = t.z, rstd = t.w;
            float px = G[NT-1].x, py = G[NT-1].y, pz = G[NT-1].z, pw = G[NT-1].w;
#pragma unroll
            for (int k = NT-2; k >= 0; k--) {
                px = fmaf(px, v, G[k].x);
                py = fmaf(py, v, G[k].y);
                pz = fmaf(pz, v, G[k].z);
                pw = fmaf(pw, v, G[k].w);
            }
            float4 o;
            o.x = fmaf((e.x + px - mu) * rstd, lw.x, lb.x);
            o.y = fmaf((e.y + py - mu) * rstd, lw.y, lb.y);
            o.z = fmaf((e.z + pz - mu) * rstd, lw.z, lb.z);
            o.w = fmaf((e.w + pw - mu) * rstd, lw.w, lb.w);
            if (enc < 0) { o.x = 0.0f; o.y = 0.0f; o.z = 0.0f; o.w = 0.0f; }
            out4[(size_t)tok * 192 + dg] = o;
        }
    }
}

// ---------------- launch --------------------------------------------------------
extern "C" void kernel_launch(void* const* d_in, const int* in_sizes, int n_in,
                              void* d_out, int out_size) {
    const float* x   = (const float*)d_in[0];
    const float* emb = (const float*)d_in[1];
    const float* w1  = (const float*)d_in[2];
    const float* b1  = (const float*)d_in[3];
    const float* w2  = (const float*)d_in[4];
    const float* b2  = (const float*)d_in[5];
    const float* lnw = (const float*)d_in[6];
    const float* lnb = (const float*)d_in[7];
    float* out = (float*)d_out;

    int write_mask = (out_size >= TOK * H + TOK) ? 1 : 0;

    coef_kernel<<<1, H>>>(w1, b1);
    gvec_kernel<<<dim3(H/128, GV_HB), 128>>>(w2, b2);
    poly_stats_kernel<<<1, H>>>();
    emb_stats_kernel<<<640, 192>>>(emb);
    topk_kernel<<<B, 1024>>>(x, out, write_mask);
    token_stats_kernel<<<TOK/256, 256>>>();
    fuse_kernel<<<TOK/FU_TPB, 192>>>(emb, lnw, lnb, out);
}

// round 5
// speedup vs baseline: 3.5934x; 1.3025x over previous
#include <cuda_runtime.h>
#include <math.h>

#define B   256
#define NF  10000
#define H   768
#define K   512
#define NT  8
#define QN  (2*NT-1)
#define TOK (B*K)

// ---------------- scratch ----------------
__device__ float g_vals[TOK];
__device__ int   g_fid[TOK];
__device__ int   g_empty[B];
__device__ __align__(16) float g_coef[NT*H];
__device__ __align__(16) float g_G[NT*H];
__device__ float g_SG[NT];
__device__ float g_Q[QN];
__device__ float g_Se[NF+1];
__device__ float g_Se2[NF+1];
__device__ __align__(16) float g_D[(NF+1)*NT];
__device__ float4 g_tok[TOK];

// ---------------- kernel 1a: per-h Taylor coefficients + zero g_G ----------------
__global__ void coef_kernel(const float* __restrict__ w1, const float* __restrict__ b1) {
    int h = threadIdx.x;
#pragma unroll
    for (int k = 0; k < NT; k++) g_G[k*H + h] = 0.0f;   // zero for gvec atomics
    double a    = (double)w1[h];
    double beta = (double)b1[h];
    const double INV_SQRT2PI = 0.39894228040143267794;
    const double INV_SQRT2   = 0.70710678118654752440;
    double phi = INV_SQRT2PI * exp(-0.5 * beta * beta);
    double Phi = 0.5 * (1.0 + erf(beta * INV_SQRT2));
    double c[NT];
    c[0] = beta * Phi;
    c[1] = (Phi + beta * phi) * a;
    double He_km2 = 1.0, He_km1 = beta, fact = 1.0, apow = a;
    for (int k = 2; k < NT; k++) {
        fact *= (double)k;
        apow *= a;
        double s  = (k & 1) ? -1.0 : 1.0;
        double gk = phi * s * ((double)k * He_km2 - beta * He_km1);
        c[k] = gk * apow / fact;
        double He_k = beta * He_km1 - (double)(k - 1) * He_km2;
        He_km2 = He_km1; He_km1 = He_k;
    }
    for (int k = 0; k < NT; k++) g_coef[k*H + h] = (float)c[k];
}

// ---------------- kernel 1b: G_k = w2^T c_k (+ b2 into k=0), h-split + atomics ---
#define GV_HB 32
#define GV_HC (H / GV_HB)
__global__ void gvec_kernel(const float* __restrict__ w2, const float* __restrict__ b2) {
    __shared__ float sc[NT * GV_HC];
    int tid = threadIdx.x;                  // 128
    int d   = blockIdx.x * 128 + tid;
    int h0  = blockIdx.y * GV_HC;
    for (int i = tid; i < NT * GV_HC; i += 128) {
        int k = i / GV_HC, h = i % GV_HC;
        sc[i] = g_coef[k*H + h0 + h];
    }
    __syncthreads();
    float acc[NT];
#pragma unroll
    for (int k = 0; k < NT; k++) acc[k] = 0.0f;
#pragma unroll 4
    for (int h = 0; h < GV_HC; h++) {
        float w = w2[(size_t)(h0 + h) * H + d];
#pragma unroll
        for (int k = 0; k < NT; k++) acc[k] = fmaf(sc[k*GV_HC + h], w, acc[k]);
    }
    if (blockIdx.y == 0) acc[0] += b2[d];
#pragma unroll
    for (int k = 0; k < NT; k++) atomicAdd(&g_G[k*H + d], acc[k]);
}

// ---------------- kernel 1c: SG_k and Q_m (1 block, 768 threads) -----------------
__global__ void poly_stats_kernel() {
    __shared__ float s[NT + NT*(NT+1)/2];
    int d = threadIdx.x;
    int lane = d & 31;
    if (d < NT + NT*(NT+1)/2) s[d] = 0.0f;
    __syncthreads();
    float g[NT];
#pragma unroll
    for (int k = 0; k < NT; k++) g[k] = g_G[k*H + d];

#define BRED(slot, expr) { float _v = (expr); \
    _v += __shfl_down_sync(0xffffffffu, _v, 16); \
    _v += __shfl_down_sync(0xffffffffu, _v, 8);  \
    _v += __shfl_down_sync(0xffffffffu, _v, 4);  \
    _v += __shfl_down_sync(0xffffffffu, _v, 2);  \
    _v += __shfl_down_sync(0xffffffffu, _v, 1);  \
    if (lane == 0) atomicAdd(&s[slot], _v); }

#pragma unroll
    for (int k = 0; k < NT; k++) BRED(k, g[k]);
    {
        int idx = NT;
#pragma unroll
        for (int k = 0; k < NT; k++)
#pragma unroll
            for (int l = k; l < NT; l++) { BRED(idx, g[k]*g[l]); idx++; }
    }
    __syncthreads();
    if (d == 0) {
        for (int k = 0; k < NT; k++) g_SG[k] = s[k];
        float q[QN];
        for (int m = 0; m < QN; m++) q[m] = 0.0f;
        int idx = NT;
        for (int k = 0; k < NT; k++)
            for (int l = k; l < NT; l++) {
                q[k+l] += (k == l ? 1.0f : 2.0f) * s[idx];
                idx++;
            }
        for (int m = 0; m < QN; m++) g_Q[m] = q[m];
    }
}

// ---------------- kernel 1d: per-emb-row Se, Se2, D_k (warp-per-row) -------------
__global__ void __launch_bounds__(256) emb_stats_kernel(const float* __restrict__ emb) {
    __shared__ float4 sG[NT * 192];         // 24 KB
    int tid  = threadIdx.x;
    int lane = tid & 31, warp = tid >> 5;   // 8 warps
    const float4* G4 = (const float4*)g_G;
    for (int i = tid; i < NT * 192; i += 256) sG[i] = G4[i];
    __syncthreads();

    const float4* emb4 = (const float4*)emb;
    int gw = blockIdx.x * 8 + warp;
    int nw = gridDim.x * 8;

    for (int r = gw; r <= NF; r += nw) {
        float s0 = 0.0f, s1 = 0.0f;
        float d[NT];
#pragma unroll
        for (int k = 0; k < NT; k++) d[k] = 0.0f;
#pragma unroll
        for (int j = 0; j < 6; j++) {
            int dg = lane + 32*j;
            float4 e = emb4[(size_t)r * 192 + dg];
            s0 += e.x + e.y + e.z + e.w;
            s1 += e.x*e.x + e.y*e.y + e.z*e.z + e.w*e.w;
#pragma unroll
            for (int k = 0; k < NT; k++) {
                float4 g = sG[k*192 + dg];
                d[k] += e.x*g.x + e.y*g.y + e.z*g.z + e.w*g.w;
            }
        }
        float vals[NT+2];
        vals[0] = s0; vals[1] = s1;
#pragma unroll
        for (int k = 0; k < NT; k++) vals[2+k] = d[k];
#pragma unroll
        for (int i = 0; i < NT+2; i++) {
            float v = vals[i];
            v += __shfl_down_sync(0xffffffffu, v, 16);
            v += __shfl_down_sync(0xffffffffu, v, 8);
            v += __shfl_down_sync(0xffffffffu, v, 4);
            v += __shfl_down_sync(0xffffffffu, v, 2);
            v += __shfl_down_sync(0xffffffffu, v, 1);
            vals[i] = v;
        }
        if (lane == 0) {
            g_Se[r]  = vals[0];
            g_Se2[r] = vals[1];
#pragma unroll
            for (int k = 0; k < NT; k++) g_D[r*NT + k] = vals[2+k];
        }
    }
}

// ---------------- kernel 2: per-row top-512 (sorted, torch tie-break) -----------
// key = (abs_bits<<32) | ~idx. Bits 63, 31..14 are constant across real keys
// (idx < 16384), so only bits 62..32 and 13..0 are searched (45 iters).
#define TK_T 512
#define TK_R 20      // 512*20 = 10240 >= NF
__global__ void __launch_bounds__(TK_T, 2) topk_kernel(const float* __restrict__ x,
                                                       float* __restrict__ out,
                                                       int write_mask) {
    __shared__ float xrow[NF];
    __shared__ unsigned long long cand[K];
    __shared__ int wsum[16];
    __shared__ int s_ge;
    __shared__ int scnt;

    int b    = blockIdx.x;
    int tid  = threadIdx.x;
    int lane = tid & 31, warp = tid >> 5;
    const float4* xr4 = (const float4*)(x + (size_t)b * NF);
    for (int i = tid; i < NF/4; i += TK_T) ((float4*)xrow)[i] = xr4[i];
    if (tid == 0) scnt = 0;
    __syncthreads();

    unsigned long long keys[TK_R];
#pragma unroll
    for (int r = 0; r < TK_R; r++) {
        int i = tid + r * TK_T;
        unsigned long long kb = 0ull;
        if (i < NF) {
            unsigned int ab = __float_as_uint(fabsf(xrow[i]));
            kb = ((unsigned long long)ab << 32) | (unsigned int)(~i);
        }
        keys[r] = kb;
    }

#define COUNT_GE(trial, res) { \
    int _c = 0; \
    _Pragma("unroll") \
    for (int _r = 0; _r < TK_R; _r++) _c += (keys[_r] >= (trial)) ? 1 : 0; \
    _c = __reduce_add_sync(0xffffffffu, _c); \
    if (lane == 0) wsum[warp] = _c; \
    __syncthreads(); \
    if (warp == 0) { \
        int _t = (lane < 16) ? wsum[lane] : 0; \
        _t = __reduce_add_sync(0xffffffffu, _t); \
        if (lane == 0) s_ge = _t; \
    } \
    __syncthreads(); \
    res = s_ge; }

    unsigned long long prefix = 0ull;
    for (int bit = 62; bit >= 32; bit--) {
        unsigned long long trial = prefix | (1ull << bit);
        int c; COUNT_GE(trial, c);
        if (c >= K) prefix = trial;
    }
    prefix |= 0xFFFFC000ull;                 // constant bits 31..14 of every real key
    for (int bit = 13; bit >= 0; bit--) {
        unsigned long long trial = prefix | (1ull << bit);
        int c; COUNT_GE(trial, c);
        if (c >= K) prefix = trial;
    }

#pragma unroll
    for (int r = 0; r < TK_R; r++) {
        if (keys[r] >= prefix) {
            int p = atomicAdd(&scnt, 1);
            if (p < K) cand[p] = keys[r];
        }
    }
    __syncthreads();

    // bitonic sort 512, descending
    for (int sz = 2; sz <= K; sz <<= 1) {
        for (int j = sz >> 1; j > 0; j >>= 1) {
            int ixj = tid ^ j;
            if (ixj > tid) {
                unsigned long long av = cand[tid], bv = cand[ixj];
                bool desc = ((tid & sz) == 0);
                if (desc ? (av < bv) : (av > bv)) { cand[tid] = bv; cand[ixj] = av; }
            }
            __syncthreads();
        }
    }

    unsigned long long key = cand[tid];
    unsigned int hi  = (unsigned int)(key >> 32);
    unsigned int idx = ~(unsigned int)key;
    int   active = (hi != 0u) ? 1 : 0;
    float val = active ? xrow[idx] : 0.0f;
    int   fid = active ? (int)idx + 1 : 0;

    int nact  = __syncthreads_count(active);
    int empty = (nact == 0) ? 1 : 0;
    g_vals[b*K + tid] = val;
    g_fid [b*K + tid] = fid;
    if (tid == 0) g_empty[b] = empty;
    if (write_mask) {
        float m = (float)active;
        if (tid == 0 && empty) m = 1.0f;
        out[(size_t)TOK * H + (size_t)b * K + tid] = m;
    }
}

// ---------------- kernel 3: closed-form per-token LN statistics ------------------
__global__ void token_stats_kernel() {
    int tok = blockIdx.x * 256 + threadIdx.x;
    float v   = g_vals[tok];
    int   fid = g_fid[tok];

    float ps = g_SG[NT-1];
#pragma unroll
    for (int k = NT-2; k >= 0; k--) ps = fmaf(ps, v, g_SG[k]);
    float sumh = g_Se[fid] + ps;

    const float4* D4 = (const float4*)&g_D[fid * NT];
    float4 d0 = D4[0], d1 = D4[1];
    float D[NT] = {d0.x, d0.y, d0.z, d0.w, d1.x, d1.y, d1.z, d1.w};
    float pd = D[NT-1];
#pragma unroll
    for (int k = NT-2; k >= 0; k--) pd = fmaf(pd, v, D[k]);
    float pq = g_Q[QN-1];
#pragma unroll
    for (int m = QN-2; m >= 0; m--) pq = fmaf(pq, v, g_Q[m]);
    float sumh2 = g_Se2[fid] + 2.0f*pd + pq;

    float mu   = sumh * (1.0f / H);
    float var  = sumh2 * (1.0f / H) - mu * mu;
    float rstd = rsqrtf(var + 1e-5f);

    unsigned int enc = (unsigned int)fid;
    if ((tok & (K-1)) == 0 && g_empty[tok >> 9]) enc |= 0x80000000u;
    g_tok[tok] = make_float4(v, __uint_as_float(enc), mu, rstd);
}

// ---------------- kernel 4: fused gather + poly + LN (reduction-free, float4) ----
#define FU_TPB 64
__global__ void __launch_bounds__(192, 4) fuse_kernel(const float* __restrict__ emb,
                                                      const float* __restrict__ lnw,
                                                      const float* __restrict__ lnb,
                                                      float* __restrict__ out) {
    int dg = threadIdx.x;                   // 0..191 -> dims 4*dg..4*dg+3
    float4 G[NT];
#pragma unroll
    for (int k = 0; k < NT; k++) G[k] = ((const float4*)g_G)[k*192 + dg];
    float4 lw = ((const float4*)lnw)[dg];
    float4 lb = ((const float4*)lnb)[dg];
    const float4* emb4 = (const float4*)emb;
    float4* out4 = (float4*)out;

    int t0 = blockIdx.x * FU_TPB;
    for (int tt = t0; tt < t0 + FU_TPB; tt += 4) {
#pragma unroll
        for (int j = 0; j < 4; j++) {
            int tok = tt + j;
            float4 t = g_tok[tok];
            int enc = __float_as_int(t.y);
            float4 e = __ldg(&emb4[(size_t)(enc & 0x7fffffff) * 192 + dg]);
            float v = t.x, mu = t.z, rstd = t.w;
            float px = G[NT-1].x, py = G[NT-1].y, pz = G[NT-1].z, pw = G[NT-1].w;
#pragma unroll
            for (int k = NT-2; k >= 0; k--) {
                px = fmaf(px, v, G[k].x);
                py = fmaf(py, v, G[k].y);
                pz = fmaf(pz, v, G[k].z);
                pw = fmaf(pw, v, G[k].w);
            }
            float4 o;
            o.x = fmaf((e.x + px - mu) * rstd, lw.x, lb.x);
            o.y = fmaf((e.y + py - mu) * rstd, lw.y, lb.y);
            o.z = fmaf((e.z + pz - mu) * rstd, lw.z, lb.z);
            o.w = fmaf((e.w + pw - mu) * rstd, lw.w, lb.w);
            if (enc < 0) { o.x = 0.0f; o.y = 0.0f; o.z = 0.0f; o.w = 0.0f; }
            __stcs(&out4[(size_t)tok * 192 + dg], o);
        }
    }
}

// ---------------- launch --------------------------------------------------------
extern "C" void kernel_launch(void* const* d_in, const int* in_sizes, int n_in,
                              void* d_out, int out_size) {
    const float* x   = (const float*)d_in[0];
    const float* emb = (const float*)d_in[1];
    const float* w1  = (const float*)d_in[2];
    const float* b1  = (const float*)d_in[3];
    const float* w2  = (const float*)d_in[4];
    const float* b2  = (const float*)d_in[5];
    const float* lnw = (const float*)d_in[6];
    const float* lnb = (const float*)d_in[7];
    float* out = (float*)d_out;

    int write_mask = (out_size >= TOK * H + TOK) ? 1 : 0;

    coef_kernel<<<1, H>>>(w1, b1);
    gvec_kernel<<<dim3(H/128, GV_HB), 128>>>(w2, b2);
    poly_stats_kernel<<<1, H>>>();
    emb_stats_kernel<<<320, 256>>>(emb);
    topk_kernel<<<B, TK_T>>>(x, out, write_mask);
    token_stats_kernel<<<TOK/256, 256>>>();
    fuse_kernel<<<TOK/FU_TPB, 192>>>(emb, lnw, lnb, out);
}

// round 6
// speedup vs baseline: 3.6237x; 1.0084x over previous
#include <cuda_runtime.h>
#include <math.h>

#define B   256
#define NF  10000
#define H   768
#define K   512
#define NT  8
#define QN  (2*NT-1)
#define TOK (B*K)

// ---------------- scratch ----------------
__device__ __align__(16) float g_coef[NT*H];
__device__ __align__(16) float g_G[NT*H];
__device__ float g_SG[NT];
__device__ float g_Q[QN];
__device__ float g_Se[NF+1];
__device__ float g_Se2[NF+1];
__device__ __align__(16) float g_D[(NF+1)*NT];
__device__ float4 g_tok[TOK];

// ---------------- kernel 1a: per-h Taylor coefficients + zero g_G ----------------
__global__ void coef_kernel(const float* __restrict__ w1, const float* __restrict__ b1) {
    int h = threadIdx.x;
#pragma unroll
    for (int k = 0; k < NT; k++) g_G[k*H + h] = 0.0f;   // zero for gvec atomics
    double a    = (double)w1[h];
    double beta = (double)b1[h];
    const double INV_SQRT2PI = 0.39894228040143267794;
    const double INV_SQRT2   = 0.70710678118654752440;
    double phi = INV_SQRT2PI * exp(-0.5 * beta * beta);
    double Phi = 0.5 * (1.0 + erf(beta * INV_SQRT2));
    double c[NT];
    c[0] = beta * Phi;
    c[1] = (Phi + beta * phi) * a;
    double He_km2 = 1.0, He_km1 = beta, fact = 1.0, apow = a;
    for (int k = 2; k < NT; k++) {
        fact *= (double)k;
        apow *= a;
        double s  = (k & 1) ? -1.0 : 1.0;
        double gk = phi * s * ((double)k * He_km2 - beta * He_km1);
        c[k] = gk * apow / fact;
        double He_k = beta * He_km1 - (double)(k - 1) * He_km2;
        He_km2 = He_km1; He_km1 = He_k;
    }
    for (int k = 0; k < NT; k++) g_coef[k*H + h] = (float)c[k];
}

// ---------------- kernel 1b: G_k = w2^T c_k (+ b2 into k=0), h-split + atomics ---
#define GV_HB 32
#define GV_HC (H / GV_HB)
__global__ void gvec_kernel(const float* __restrict__ w2, const float* __restrict__ b2) {
    __shared__ float sc[NT * GV_HC];
    int tid = threadIdx.x;                  // 128
    int d   = blockIdx.x * 128 + tid;
    int h0  = blockIdx.y * GV_HC;
    for (int i = tid; i < NT * GV_HC; i += 128) {
        int k = i / GV_HC, h = i % GV_HC;
        sc[i] = g_coef[k*H + h0 + h];
    }
    __syncthreads();
    float acc[NT];
#pragma unroll
    for (int k = 0; k < NT; k++) acc[k] = 0.0f;
#pragma unroll 4
    for (int h = 0; h < GV_HC; h++) {
        float w = w2[(size_t)(h0 + h) * H + d];
#pragma unroll
        for (int k = 0; k < NT; k++) acc[k] = fmaf(sc[k*GV_HC + h], w, acc[k]);
    }
    if (blockIdx.y == 0) acc[0] += b2[d];
#pragma unroll
    for (int k = 0; k < NT; k++) atomicAdd(&g_G[k*H + d], acc[k]);
}

// ---------------- kernel 1c: SG_k and Q_m (1 block, 768 threads) -----------------
__global__ void poly_stats_kernel() {
    __shared__ float s[NT + NT*(NT+1)/2];
    int d = threadIdx.x;
    int lane = d & 31;
    if (d < NT + NT*(NT+1)/2) s[d] = 0.0f;
    __syncthreads();
    float g[NT];
#pragma unroll
    for (int k = 0; k < NT; k++) g[k] = g_G[k*H + d];

#define BRED(slot, expr) { float _v = (expr); \
    _v += __shfl_down_sync(0xffffffffu, _v, 16); \
    _v += __shfl_down_sync(0xffffffffu, _v, 8);  \
    _v += __shfl_down_sync(0xffffffffu, _v, 4);  \
    _v += __shfl_down_sync(0xffffffffu, _v, 2);  \
    _v += __shfl_down_sync(0xffffffffu, _v, 1);  \
    if (lane == 0) atomicAdd(&s[slot], _v); }

#pragma unroll
    for (int k = 0; k < NT; k++) BRED(k, g[k]);
    {
        int idx = NT;
#pragma unroll
        for (int k = 0; k < NT; k++)
#pragma unroll
            for (int l = k; l < NT; l++) { BRED(idx, g[k]*g[l]); idx++; }
    }
    __syncthreads();
    if (d == 0) {
        for (int k = 0; k < NT; k++) g_SG[k] = s[k];
        float q[QN];
        for (int m = 0; m < QN; m++) q[m] = 0.0f;
        int idx = NT;
        for (int k = 0; k < NT; k++)
            for (int l = k; l < NT; l++) {
                q[k+l] += (k == l ? 1.0f : 2.0f) * s[idx];
                idx++;
            }
        for (int m = 0; m < QN; m++) g_Q[m] = q[m];
    }
}

// ---------------- kernel 1d: per-emb-row Se, Se2, D_k (warp-per-row) -------------
__global__ void __launch_bounds__(256, 4) emb_stats_kernel(const float* __restrict__ emb) {
    __shared__ float4 sG[NT * 192];         // 24 KB
    int tid  = threadIdx.x;
    int lane = tid & 31, warp = tid >> 5;   // 8 warps
    const float4* G4 = (const float4*)g_G;
    for (int i = tid; i < NT * 192; i += 256) sG[i] = G4[i];
    __syncthreads();

    const float4* emb4 = (const float4*)emb;
    int gw = blockIdx.x * 8 + warp;
    int nw = gridDim.x * 8;

    for (int r = gw; r <= NF; r += nw) {
        float s0 = 0.0f, s1 = 0.0f;
        float d[NT];
#pragma unroll
        for (int k = 0; k < NT; k++) d[k] = 0.0f;
#pragma unroll 2
        for (int j = 0; j < 6; j++) {
            int dg = lane + 32*j;
            float4 e = emb4[(size_t)r * 192 + dg];
            s0 += e.x + e.y + e.z + e.w;
            s1 += e.x*e.x + e.y*e.y + e.z*e.z + e.w*e.w;
#pragma unroll
            for (int k = 0; k < NT; k++) {
                float4 g = sG[k*192 + dg];
                d[k] += e.x*g.x + e.y*g.y + e.z*g.z + e.w*g.w;
            }
        }
        float vals[NT+2];
        vals[0] = s0; vals[1] = s1;
#pragma unroll
        for (int k = 0; k < NT; k++) vals[2+k] = d[k];
#pragma unroll
        for (int i = 0; i < NT+2; i++) {
            float v = vals[i];
            v += __shfl_down_sync(0xffffffffu, v, 16);
            v += __shfl_down_sync(0xffffffffu, v, 8);
            v += __shfl_down_sync(0xffffffffu, v, 4);
            v += __shfl_down_sync(0xffffffffu, v, 2);
            v += __shfl_down_sync(0xffffffffu, v, 1);
            vals[i] = v;
        }
        if (lane == 0) {
            g_Se[r]  = vals[0];
            g_Se2[r] = vals[1];
#pragma unroll
            for (int k = 0; k < NT; k++) g_D[r*NT + k] = vals[2+k];
        }
    }
}

// ---------------- kernel 2: top-512 + fused closed-form LN stats -----------------
// key = (abs_bits<<32) | ~idx. Bits 63, 31..14 constant across real keys.
#define TK_T 512
#define TK_R 20      // 512*20 = 10240 >= NF
__global__ void __launch_bounds__(TK_T, 2) topk_kernel(const float* __restrict__ x,
                                                       float* __restrict__ out,
                                                       int write_mask) {
    __shared__ float xrow[NF];
    __shared__ unsigned long long cand[K];
    __shared__ int wsum[16];
    __shared__ int s_ge;
    __shared__ int scnt;

    int b    = blockIdx.x;
    int tid  = threadIdx.x;
    int lane = tid & 31, warp = tid >> 5;
    const float4* xr4 = (const float4*)(x + (size_t)b * NF);
    for (int i = tid; i < NF/4; i += TK_T) ((float4*)xrow)[i] = xr4[i];
    if (tid == 0) scnt = 0;
    __syncthreads();

    unsigned long long keys[TK_R];
#pragma unroll
    for (int r = 0; r < TK_R; r++) {
        int i = tid + r * TK_T;
        unsigned long long kb = 0ull;
        if (i < NF) {
            unsigned int ab = __float_as_uint(fabsf(xrow[i]));
            kb = ((unsigned long long)ab << 32) | (unsigned int)(~i);
        }
        keys[r] = kb;
    }

#define COUNT_GE(trial, res) { \
    int _c = 0; \
    _Pragma("unroll") \
    for (int _r = 0; _r < TK_R; _r++) _c += (keys[_r] >= (trial)) ? 1 : 0; \
    _c = __reduce_add_sync(0xffffffffu, _c); \
    if (lane == 0) wsum[warp] = _c; \
    __syncthreads(); \
    if (warp == 0) { \
        int _t = (lane < 16) ? wsum[lane] : 0; \
        _t = __reduce_add_sync(0xffffffffu, _t); \
        if (lane == 0) s_ge = _t; \
    } \
    __syncthreads(); \
    res = s_ge; }

    unsigned long long prefix = 0ull;
    for (int bit = 62; bit >= 32; bit--) {
        unsigned long long trial = prefix | (1ull << bit);
        int c; COUNT_GE(trial, c);
        if (c >= K) prefix = trial;
    }
    prefix |= 0xFFFFC000ull;                 // constant bits 31..14 of every real key
    for (int bit = 13; bit >= 0; bit--) {
        unsigned long long trial = prefix | (1ull << bit);
        int c; COUNT_GE(trial, c);
        if (c >= K) prefix = trial;
    }

#pragma unroll
    for (int r = 0; r < TK_R; r++) {
        if (keys[r] >= prefix) {
            int p = atomicAdd(&scnt, 1);
            if (p < K) cand[p] = keys[r];
        }
    }
    __syncthreads();

    // bitonic sort 512, descending
    for (int sz = 2; sz <= K; sz <<= 1) {
        for (int j = sz >> 1; j > 0; j >>= 1) {
            int ixj = tid ^ j;
            if (ixj > tid) {
                unsigned long long av = cand[tid], bv = cand[ixj];
                bool desc = ((tid & sz) == 0);
                if (desc ? (av < bv) : (av > bv)) { cand[tid] = bv; cand[ixj] = av; }
            }
            __syncthreads();
        }
    }

    unsigned long long key = cand[tid];
    unsigned int hi  = (unsigned int)(key >> 32);
    unsigned int idx = ~(unsigned int)key;
    int   active = (hi != 0u) ? 1 : 0;
    float v   = active ? xrow[idx] : 0.0f;
    int   fid = active ? (int)idx + 1 : 0;

    int nact  = __syncthreads_count(active);
    int empty = (nact == 0) ? 1 : 0;

    // ---- fused closed-form LN stats for this token ----
    float ps = g_SG[NT-1];
#pragma unroll
    for (int k = NT-2; k >= 0; k--) ps = fmaf(ps, v, g_SG[k]);
    float sumh = g_Se[fid] + ps;

    const float4* D4 = (const float4*)&g_D[fid * NT];
    float4 d0 = D4[0], d1 = D4[1];
    float D[NT] = {d0.x, d0.y, d0.z, d0.w, d1.x, d1.y, d1.z, d1.w};
    float pd = D[NT-1];
#pragma unroll
    for (int k = NT-2; k >= 0; k--) pd = fmaf(pd, v, D[k]);
    float pq = g_Q[QN-1];
#pragma unroll
    for (int m = QN-2; m >= 0; m--) pq = fmaf(pq, v, g_Q[m]);
    float sumh2 = g_Se2[fid] + 2.0f*pd + pq;

    float mu   = sumh * (1.0f / H);
    float var  = sumh2 * (1.0f / H) - mu * mu;
    float rstd = rsqrtf(var + 1e-5f);

    unsigned int enc = (unsigned int)fid;
    if (tid == 0 && empty) enc |= 0x80000000u;
    g_tok[b*K + tid] = make_float4(v, __uint_as_float(enc), mu, rstd);

    if (write_mask) {
        float m = (float)active;
        if (tid == 0 && empty) m = 1.0f;
        out[(size_t)TOK * H + (size_t)b * K + tid] = m;
    }
}

// ---------------- kernel 3: fused gather + poly + LN (reduction-free, float4) ----
#define FU_TPB 64
__global__ void __launch_bounds__(192, 5) fuse_kernel(const float* __restrict__ emb,
                                                      const float* __restrict__ lnw,
                                                      const float* __restrict__ lnb,
                                                      float* __restrict__ out) {
    int dg = threadIdx.x;                   // 0..191 -> dims 4*dg..4*dg+3
    float4 G[NT];
#pragma unroll
    for (int k = 0; k < NT; k++) G[k] = ((const float4*)g_G)[k*192 + dg];
    float4 lw = ((const float4*)lnw)[dg];
    float4 lb = ((const float4*)lnb)[dg];
    const float4* emb4 = (const float4*)emb;
    float4* out4 = (float4*)out;

    int t0 = blockIdx.x * FU_TPB;
    for (int tt = t0; tt < t0 + FU_TPB; tt += 4) {
#pragma unroll
        for (int j = 0; j < 4; j++) {
            int tok = tt + j;
            float4 t = g_tok[tok];
            int enc = __float_as_int(t.y);
            float4 e = __ldg(&emb4[(size_t)(enc & 0x7fffffff) * 192 + dg]);
            float v = t.x, mu = t.z, rstd = t.w;
            float px = G[NT-1].x, py = G[NT-1].y, pz = G[NT-1].z, pw = G[NT-1].w;
#pragma unroll
            for (int k = NT-2; k >= 0; k--) {
                px = fmaf(px, v, G[k].x);
                py = fmaf(py, v, G[k].y);
                pz = fmaf(pz, v, G[k].z);
                pw = fmaf(pw, v, G[k].w);
            }
            float4 o;
            o.x = fmaf((e.x + px - mu) * rstd, lw.x, lb.x);
            o.y = fmaf((e.y + py - mu) * rstd, lw.y, lb.y);
            o.z = fmaf((e.z + pz - mu) * rstd, lw.z, lb.z);
            o.w = fmaf((e.w + pw - mu) * rstd, lw.w, lb.w);
            if (enc < 0) { o.x = 0.0f; o.y = 0.0f; o.z = 0.0f; o.w = 0.0f; }
            __stcs(&out4[(size_t)tok * 192 + dg], o);
        }
    }
}

// ---------------- launch --------------------------------------------------------
extern "C" void kernel_launch(void* const* d_in, const int* in_sizes, int n_in,
                              void* d_out, int out_size) {
    const float* x   = (const float*)d_in[0];
    const float* emb = (const float*)d_in[1];
    const float* w1  = (const float*)d_in[2];
    const float* b1  = (const float*)d_in[3];
    const float* w2  = (const float*)d_in[4];
    const float* b2  = (const float*)d_in[5];
    const float* lnw = (const float*)d_in[6];
    const float* lnb = (const float*)d_in[7];
    float* out = (float*)d_out;

    int write_mask = (out_size >= TOK * H + TOK) ? 1 : 0;

    coef_kernel<<<1, H>>>(w1, b1);
    gvec_kernel<<<dim3(H/128, GV_HB), 128>>>(w2, b2);
    poly_stats_kernel<<<1, H>>>();
    emb_stats_kernel<<<640, 256>>>(emb);
    topk_kernel<<<B, TK_T>>>(x, out, write_mask);
    fuse_kernel<<<TOK/FU_TPB, 192>>>(emb, lnw, lnb, out);
}

// round 7
// speedup vs baseline: 4.7592x; 1.3134x over previous
#include <cuda_runtime.h>
#include <math.h>

#define B   256
#define NF  10000
#define H   768
#define K   512
#define NT  8
#define QN  (2*NT-1)
#define TOK (B*K)

// ---------------- scratch ----------------
__device__ __align__(16) float g_G[NT*H];
__device__ float g_SG[NT];
__device__ float g_Q[QN];
__device__ float g_Se[NF+1];
__device__ float g_Se2[NF+1];
__device__ __align__(16) float g_D[(NF+1)*NT];
__device__ float4 g_tok[TOK];

// ---------------- kernel 0: zero g_G for gvec atomics ---------------------------
__global__ void zero_G_kernel() {
    int i = blockIdx.x * 1024 + threadIdx.x;
    if (i < NT*H) g_G[i] = 0.0f;
}

// ---------------- kernel 1: G_k = w2^T c_k (+ b2 into k=0) ----------------------
// Taylor coefficients of gelu(w1[h]*v + b1[h]) computed inline in fp32 per block
// (24 h-values per block, redundant across x-blocks — trivially cheap, and it
// removes the serial single-SM fp64 coef kernel entirely).
#define GV_HB 32
#define GV_HC (H / GV_HB)
__global__ void gvec_kernel(const float* __restrict__ w1, const float* __restrict__ b1,
                            const float* __restrict__ w2, const float* __restrict__ b2) {
    __shared__ float sc[NT * GV_HC];
    int tid = threadIdx.x;                  // 128
    int d   = blockIdx.x * 128 + tid;
    int h0  = blockIdx.y * GV_HC;

    if (tid < GV_HC) {
        int h = h0 + tid;
        float a    = w1[h];
        float beta = b1[h];
        float phi = 0.3989422804f * expf(-0.5f * beta * beta);
        float Phi = 0.5f * (1.0f + erff(beta * 0.7071067812f));
        sc[0*GV_HC + tid] = beta * Phi;                 // gelu(beta)
        sc[1*GV_HC + tid] = (Phi + beta * phi) * a;     // gelu'(beta)*a
        float He_km2 = 1.0f, He_km1 = beta, fact = 1.0f, apow = a;
#pragma unroll
        for (int k = 2; k < NT; k++) {
            fact *= (float)k;
            apow *= a;
            float s  = (k & 1) ? -1.0f : 1.0f;
            float gk = phi * s * ((float)k * He_km2 - beta * He_km1);
            sc[k*GV_HC + tid] = gk * apow / fact;
            float He_k = beta * He_km1 - (float)(k - 1) * He_km2;
            He_km2 = He_km1; He_km1 = He_k;
        }
    }
    __syncthreads();

    float acc[NT];
#pragma unroll
    for (int k = 0; k < NT; k++) acc[k] = 0.0f;
#pragma unroll 4
    for (int h = 0; h < GV_HC; h++) {
        float w = w2[(size_t)(h0 + h) * H + d];
#pragma unroll
        for (int k = 0; k < NT; k++) acc[k] = fmaf(sc[k*GV_HC + h], w, acc[k]);
    }
    if (blockIdx.y == 0) acc[0] += b2[d];
#pragma unroll
    for (int k = 0; k < NT; k++) atomicAdd(&g_G[k*H + d], acc[k]);
}

// ---------------- kernel 1c: SG_k and Q_m (1 block, 768 threads) -----------------
__global__ void poly_stats_kernel() {
    __shared__ float s[NT + NT*(NT+1)/2];
    int d = threadIdx.x;
    int lane = d & 31;
    if (d < NT + NT*(NT+1)/2) s[d] = 0.0f;
    __syncthreads();
    float g[NT];
#pragma unroll
    for (int k = 0; k < NT; k++) g[k] = g_G[k*H + d];

#define BRED(slot, expr) { float _v = (expr); \
    _v += __shfl_down_sync(0xffffffffu, _v, 16); \
    _v += __shfl_down_sync(0xffffffffu, _v, 8);  \
    _v += __shfl_down_sync(0xffffffffu, _v, 4);  \
    _v += __shfl_down_sync(0xffffffffu, _v, 2);  \
    _v += __shfl_down_sync(0xffffffffu, _v, 1);  \
    if (lane == 0) atomicAdd(&s[slot], _v); }

#pragma unroll
    for (int k = 0; k < NT; k++) BRED(k, g[k]);
    {
        int idx = NT;
#pragma unroll
        for (int k = 0; k < NT; k++)
#pragma unroll
            for (int l = k; l < NT; l++) { BRED(idx, g[k]*g[l]); idx++; }
    }
    __syncthreads();
    if (d == 0) {
        for (int k = 0; k < NT; k++) g_SG[k] = s[k];
        float q[QN];
        for (int m = 0; m < QN; m++) q[m] = 0.0f;
        int idx = NT;
        for (int k = 0; k < NT; k++)
            for (int l = k; l < NT; l++) {
                q[k+l] += (k == l ? 1.0f : 2.0f) * s[idx];
                idx++;
            }
        for (int m = 0; m < QN; m++) g_Q[m] = q[m];
    }
}

// ---------------- kernel 1d: per-emb-row Se, Se2, D_k (warp x 4 rows) ------------
__global__ void __launch_bounds__(256, 3) emb_stats_kernel(const float* __restrict__ emb) {
    __shared__ float4 sG[NT * 192];         // 24 KB
    int tid  = threadIdx.x;
    int lane = tid & 31, warp = tid >> 5;   // 8 warps
    const float4* G4 = (const float4*)g_G;
    for (int i = tid; i < NT * 192; i += 256) sG[i] = G4[i];
    __syncthreads();

    int r0 = (blockIdx.x * 8 + warp) * 4;
    if (r0 > NF) return;
    int nrow = NF + 1 - r0; if (nrow > 4) nrow = 4;

    const float4* emb4 = (const float4*)emb;
    float acc[4][NT+2];
#pragma unroll
    for (int t = 0; t < 4; t++)
#pragma unroll
        for (int i = 0; i < NT+2; i++) acc[t][i] = 0.0f;

#pragma unroll
    for (int j = 0; j < 6; j++) {
        int dg = lane + 32*j;
        float4 e[4];
#pragma unroll
        for (int t = 0; t < 4; t++)
            e[t] = (t < nrow) ? __ldg(&emb4[(size_t)(r0 + t) * 192 + dg])
                              : make_float4(0.f, 0.f, 0.f, 0.f);
#pragma unroll
        for (int t = 0; t < 4; t++) {
            acc[t][0] += e[t].x + e[t].y + e[t].z + e[t].w;
            acc[t][1] += e[t].x*e[t].x + e[t].y*e[t].y + e[t].z*e[t].z + e[t].w*e[t].w;
        }
#pragma unroll
        for (int k = 0; k < NT; k++) {
            float4 g = sG[k*192 + dg];
#pragma unroll
            for (int t = 0; t < 4; t++)
                acc[t][2+k] += e[t].x*g.x + e[t].y*g.y + e[t].z*g.z + e[t].w*g.w;
        }
    }
#pragma unroll
    for (int t = 0; t < 4; t++)
#pragma unroll
        for (int i = 0; i < NT+2; i++) {
            float v = acc[t][i];
            v += __shfl_down_sync(0xffffffffu, v, 16);
            v += __shfl_down_sync(0xffffffffu, v, 8);
            v += __shfl_down_sync(0xffffffffu, v, 4);
            v += __shfl_down_sync(0xffffffffu, v, 2);
            v += __shfl_down_sync(0xffffffffu, v, 1);
            acc[t][i] = v;
        }
    if (lane == 0) {
        for (int t = 0; t < nrow; t++) {
            int r = r0 + t;
            g_Se[r]  = acc[t][0];
            g_Se2[r] = acc[t][1];
            float4* D4 = (float4*)&g_D[r * NT];
            D4[0] = make_float4(acc[t][2], acc[t][3], acc[t][4], acc[t][5]);
            D4[1] = make_float4(acc[t][6], acc[t][7], acc[t][8], acc[t][9]);
        }
    }
}

// ---------------- kernel 2: top-512 + fused closed-form LN stats -----------------
// key = (abs_bits<<32) | ~idx. Bits 63, 31..14 constant across real keys.
#define TK_T 512
#define TK_R 20      // 512*20 = 10240 >= NF
__global__ void __launch_bounds__(TK_T, 2) topk_kernel(const float* __restrict__ x,
                                                       float* __restrict__ out,
                                                       int write_mask) {
    __shared__ float xrow[NF];
    __shared__ unsigned long long cand[K];
    __shared__ int wsum[16];
    __shared__ int s_ge;
    __shared__ int scnt;

    int b    = blockIdx.x;
    int tid  = threadIdx.x;
    int lane = tid & 31, warp = tid >> 5;
    const float4* xr4 = (const float4*)(x + (size_t)b * NF);
    for (int i = tid; i < NF/4; i += TK_T) ((float4*)xrow)[i] = xr4[i];
    if (tid == 0) scnt = 0;
    __syncthreads();

    unsigned long long keys[TK_R];
#pragma unroll
    for (int r = 0; r < TK_R; r++) {
        int i = tid + r * TK_T;
        unsigned long long kb = 0ull;
        if (i < NF) {
            unsigned int ab = __float_as_uint(fabsf(xrow[i]));
            kb = ((unsigned long long)ab << 32) | (unsigned int)(~i);
        }
        keys[r] = kb;
    }

#define COUNT_GE(trial, res) { \
    int _c = 0; \
    _Pragma("unroll") \
    for (int _r = 0; _r < TK_R; _r++) _c += (keys[_r] >= (trial)) ? 1 : 0; \
    _c = __reduce_add_sync(0xffffffffu, _c); \
    if (lane == 0) wsum[warp] = _c; \
    __syncthreads(); \
    if (warp == 0) { \
        int _t = (lane < 16) ? wsum[lane] : 0; \
        _t = __reduce_add_sync(0xffffffffu, _t); \
        if (lane == 0) s_ge = _t; \
    } \
    __syncthreads(); \
    res = s_ge; }

    unsigned long long prefix = 0ull;
    for (int bit = 62; bit >= 32; bit--) {
        unsigned long long trial = prefix | (1ull << bit);
        int c; COUNT_GE(trial, c);
        if (c >= K) prefix = trial;
    }
    // abs part resolved; if the count at this pivot is exactly K (no abs ties,
    // the statistically certain case) the 14 tie-break rounds are unnecessary.
    int c0; COUNT_GE(prefix, c0);
    if (c0 != K) {
        prefix |= 0xFFFFC000ull;            // constant bits 31..14 of every real key
        for (int bit = 13; bit >= 0; bit--) {
            unsigned long long trial = prefix | (1ull << bit);
            int c; COUNT_GE(trial, c);
            if (c >= K) prefix = trial;
        }
    }

#pragma unroll
    for (int r = 0; r < TK_R; r++) {
        if (keys[r] >= prefix) {
            int p = atomicAdd(&scnt, 1);
            if (p < K) cand[p] = keys[r];
        }
    }
    __syncthreads();

    // bitonic sort 512, descending
    for (int sz = 2; sz <= K; sz <<= 1) {
        for (int j = sz >> 1; j > 0; j >>= 1) {
            int ixj = tid ^ j;
            if (ixj > tid) {
                unsigned long long av = cand[tid], bv = cand[ixj];
                bool desc = ((tid & sz) == 0);
                if (desc ? (av < bv) : (av > bv)) { cand[tid] = bv; cand[ixj] = av; }
            }
            __syncthreads();
        }
    }

    unsigned long long key = cand[tid];
    unsigned int hi  = (unsigned int)(key >> 32);
    unsigned int idx = ~(unsigned int)key;
    int   active = (hi != 0u) ? 1 : 0;
    float v   = active ? xrow[idx] : 0.0f;
    int   fid = active ? (int)idx + 1 : 0;

    int nact  = __syncthreads_count(active);
    int empty = (nact == 0) ? 1 : 0;

    // ---- fused closed-form LN stats for this token ----
    float ps = g_SG[NT-1];
#pragma unroll
    for (int k = NT-2; k >= 0; k--) ps = fmaf(ps, v, g_SG[k]);
    float sumh = g_Se[fid] + ps;

    const float4* D4 = (const float4*)&g_D[fid * NT];
    float4 d0 = D4[0], d1 = D4[1];
    float D[NT] = {d0.x, d0.y, d0.z, d0.w, d1.x, d1.y, d1.z, d1.w};
    float pd = D[NT-1];
#pragma unroll
    for (int k = NT-2; k >= 0; k--) pd = fmaf(pd, v, D[k]);
    float pq = g_Q[QN-1];
#pragma unroll
    for (int m = QN-2; m >= 0; m--) pq = fmaf(pq, v, g_Q[m]);
    float sumh2 = g_Se2[fid] + 2.0f*pd + pq;

    float mu   = sumh * (1.0f / H);
    float var  = sumh2 * (1.0f / H) - mu * mu;
    float rstd = rsqrtf(var + 1e-5f);

    unsigned int enc = (unsigned int)fid;
    if (tid == 0 && empty) enc |= 0x80000000u;
    g_tok[b*K + tid] = make_float4(v, __uint_as_float(enc), mu, rstd);

    if (write_mask) {
        float m = (float)active;
        if (tid == 0 && empty) m = 1.0f;
        out[(size_t)TOK * H + (size_t)b * K + tid] = m;
    }
}

// ---------------- kernel 3: fused gather + poly + LN (reduction-free, float4) ----
#define FU_TPB 64
__global__ void __launch_bounds__(192, 5) fuse_kernel(const float* __restrict__ emb,
                                                      const float* __restrict__ lnw,
                                                      const float* __restrict__ lnb,
                                                      float* __restrict__ out) {
    int dg = threadIdx.x;                   // 0..191 -> dims 4*dg..4*dg+3
    float4 G[NT];
#pragma unroll
    for (int k = 0; k < NT; k++) G[k] = ((const float4*)g_G)[k*192 + dg];
    float4 lw = ((const float4*)lnw)[dg];
    float4 lb = ((const float4*)lnb)[dg];
    const float4* emb4 = (const float4*)emb;
    float4* out4 = (float4*)out;

    int t0 = blockIdx.x * FU_TPB;
    for (int tt = t0; tt < t0 + FU_TPB; tt += 4) {
#pragma unroll
        for (int j = 0; j < 4; j++) {
            int tok = tt + j;
            float4 t = g_tok[tok];
            int enc = __float_as_int(t.y);
            float4 e = __ldg(&emb4[(size_t)(enc & 0x7fffffff) * 192 + dg]);
            float v = t.x, mu = t.z, rstd = t.w;
            float px = G[NT-1].x, py = G[NT-1].y, pz = G[NT-1].z, pw = G[NT-1].w;
#pragma unroll
            for (int k = NT-2; k >= 0; k--) {
                px = fmaf(px, v, G[k].x);
                py = fmaf(py, v, G[k].y);
                pz = fmaf(pz, v, G[k].z);
                pw = fmaf(pw, v, G[k].w);
            }
            float4 o;
            o.x = fmaf((e.x + px - mu) * rstd, lw.x, lb.x);
            o.y = fmaf((e.y + py - mu) * rstd, lw.y, lb.y);
            o.z = fmaf((e.z + pz - mu) * rstd, lw.z, lb.z);
            o.w = fmaf((e.w + pw - mu) * rstd, lw.w, lb.w);
            if (enc < 0) { o.x = 0.0f; o.y = 0.0f; o.z = 0.0f; o.w = 0.0f; }
            __stcs(&out4[(size_t)tok * 192 + dg], o);
        }
    }
}

// ---------------- launch --------------------------------------------------------
extern "C" void kernel_launch(void* const* d_in, const int* in_sizes, int n_in,
                              void* d_out, int out_size) {
    const float* x   = (const float*)d_in[0];
    const float* emb = (const float*)d_in[1];
    const float* w1  = (const float*)d_in[2];
    const float* b1  = (const float*)d_in[3];
    const float* w2  = (const float*)d_in[4];
    const float* b2  = (const float*)d_in[5];
    const float* lnw = (const float*)d_in[6];
    const float* lnb = (const float*)d_in[7];
    float* out = (float*)d_out;

    int write_mask = (out_size >= TOK * H + TOK) ? 1 : 0;

    zero_G_kernel<<<6, 1024>>>();
    gvec_kernel<<<dim3(H/128, GV_HB), 128>>>(w1, b1, w2, b2);
    poly_stats_kernel<<<1, H>>>();
    emb_stats_kernel<<<313, 256>>>(emb);
    topk_kernel<<<B, TK_T>>>(x, out, write_mask);
    fuse_kernel<<<TOK/FU_TPB, 192>>>(emb, lnw, lnb, out);
}